// round 1
// baseline (speedup 1.0000x reference)
#include <cuda_runtime.h>

#define NUM_G 4096
#define D4    32          // 128 floats = 32 float4 per row
#define TPB   512
#define RG    16          // row groups in pass 1 (TPB / 32)
#define EPSV  1e-5f

__device__ int g_seg_off[NUM_G + 1];

// One thread per graph boundary: binary search lower_bound(g) over sorted batch.
// Runtime dtype detection: if batch is int64 (LE), odd 32-bit words near the end
// are high words of values < 4096 -> all zero. If int32, the tail values ~4095.
__global__ void offsets_kernel(const int* __restrict__ b32, int n)
{
    int g = blockIdx.x * blockDim.x + threadIdx.x;
    if (g > NUM_G) return;
    int probe = b32[n - 1] | b32[n - 3] | b32[n - 5] | b32[n - 7];
    int sh = (probe == 0) ? 1 : 0;   // 1 => int64, read low words at stride 2
    int lo = 0, hi = n;
    while (lo < hi) {
        int mid = (lo + hi) >> 1;
        int v = b32[(long long)mid << sh];
        if (v < g) lo = mid + 1; else hi = mid;
    }
    g_seg_off[g] = lo;
}

__global__ __launch_bounds__(TPB) void graphnorm_kernel(
    const float4* __restrict__ x4,
    const float*  __restrict__ weight,
    const float*  __restrict__ bias,
    float4*       __restrict__ out4)
{
    __shared__ float4 red_s[RG][D4];
    __shared__ float4 red_q[RG][D4];
    __shared__ float4 sc_s[D4];
    __shared__ float4 sh_s[D4];

    const int g   = blockIdx.x;
    const int tid = threadIdx.x;
    const int c4  = tid & (D4 - 1);   // float4 column
    const int rg  = tid >> 5;         // row group 0..15

    const int start = g_seg_off[g];
    const int end   = g_seg_off[g + 1];
    const int cnt   = end - start;

    // ---- Pass 1: per-column sum / sumsq ----
    float4 s = make_float4(0.f, 0.f, 0.f, 0.f);
    float4 q = make_float4(0.f, 0.f, 0.f, 0.f);
    for (int r = start + rg; r < end; r += RG) {
        float4 v = x4[r * D4 + c4];
        s.x += v.x; s.y += v.y; s.z += v.z; s.w += v.w;
        q.x += v.x * v.x; q.y += v.y * v.y;
        q.z += v.z * v.z; q.w += v.w * v.w;
    }
    red_s[rg][c4] = s;
    red_q[rg][c4] = q;
    __syncthreads();

    #pragma unroll
    for (int h = RG / 2; h >= 1; h >>= 1) {
        if (rg < h) {
            float4 a = red_s[rg][c4], b = red_s[rg + h][c4];
            a.x += b.x; a.y += b.y; a.z += b.z; a.w += b.w;
            red_s[rg][c4] = a;
            float4 c = red_q[rg][c4], d = red_q[rg + h][c4];
            c.x += d.x; c.y += d.y; c.z += d.z; c.w += d.w;
            red_q[rg][c4] = c;
        }
        __syncthreads();
    }

    // ---- Fold into scale/shift (warp 0) ----
    if (rg == 0) {
        float4 w = reinterpret_cast<const float4*>(weight)[c4];
        float4 b = reinterpret_cast<const float4*>(bias)[c4];
        float4 sc, sh;
        if (cnt > 1) {
            float4 S = red_s[0][c4];
            float4 Q = red_q[0][c4];
            float inv_n = 1.0f / (float)cnt;
            float mx = S.x * inv_n, my = S.y * inv_n, mz = S.z * inv_n, mw = S.w * inv_n;
            float vx = Q.x * inv_n - mx * mx;
            float vy = Q.y * inv_n - my * my;
            float vz = Q.z * inv_n - mz * mz;
            float vw = Q.w * inv_n - mw * mw;
            sc.x = w.x * rsqrtf(vx + EPSV);
            sc.y = w.y * rsqrtf(vy + EPSV);
            sc.z = w.z * rsqrtf(vz + EPSV);
            sc.w = w.w * rsqrtf(vw + EPSV);
            sh.x = b.x - mx * sc.x;
            sh.y = b.y - my * sc.y;
            sh.z = b.z - mz * sc.z;
            sh.w = b.w - mw * sc.w;
        } else {
            // cnt <= 1: reference leaves mean=0, var=1
            float r = rsqrtf(1.0f + EPSV);
            sc.x = w.x * r; sc.y = w.y * r; sc.z = w.z * r; sc.w = w.w * r;
            sh = b;
        }
        sc_s[c4] = sc;
        sh_s[c4] = sh;
    }
    __syncthreads();

    // ---- Pass 2: normalize (x re-read should hit L1/L2) ----
    const int jend = end * D4;
    for (int j = start * D4 + tid; j < jend; j += TPB) {
        int c = j & (D4 - 1);
        float4 v  = x4[j];
        float4 sc = sc_s[c];
        float4 sh = sh_s[c];
        float4 o;
        o.x = v.x * sc.x + sh.x;
        o.y = v.y * sc.y + sh.y;
        o.z = v.z * sc.z + sh.z;
        o.w = v.w * sc.w + sh.w;
        out4[j] = o;
    }
}

extern "C" void kernel_launch(void* const* d_in, const int* in_sizes, int n_in,
                              void* d_out, int out_size)
{
    const float* x      = (const float*)d_in[0];
    const int*   batch  = (const int*)d_in[1];   // int32 or int64; detected on device
    const float* weight = (const float*)d_in[2];
    const float* bias   = (const float*)d_in[3];
    float*       out    = (float*)d_out;

    int n = in_sizes[1];  // number of nodes

    offsets_kernel<<<(NUM_G + 1 + 255) / 256, 256>>>(batch, n);
    graphnorm_kernel<<<NUM_G, TPB>>>(
        reinterpret_cast<const float4*>(x), weight, bias,
        reinterpret_cast<float4*>(out));
}

// round 2
// speedup vs baseline: 1.0636x; 1.0636x over previous
#include <cuda_runtime.h>

#define NUM_G 4096
#define D4    32          // 128 floats = 32 float4 per row
#define TPB   512
#define RG    16          // row groups in pass 1 (TPB / 32)
#define EPSV  1e-5f

__device__ int g_seg_off[NUM_G + 1];

// One thread per graph boundary: binary search lower_bound(g) over sorted batch.
// Runtime dtype detection: if batch is int64 (LE), odd 32-bit words near the end
// are high words of values < 4096 -> all zero. If int32, the tail values ~4095.
__global__ void offsets_kernel(const int* __restrict__ b32, int n)
{
    int g = blockIdx.x * blockDim.x + threadIdx.x;
    if (g > NUM_G) return;
    int probe = b32[n - 1] | b32[n - 3] | b32[n - 5] | b32[n - 7];
    int sh = (probe == 0) ? 1 : 0;   // 1 => int64, read low words at stride 2
    int lo = 0, hi = n;
    while (lo < hi) {
        int mid = (lo + hi) >> 1;
        int v = b32[(long long)mid << sh];
        if (v < g) lo = mid + 1; else hi = mid;
    }
    g_seg_off[g] = lo;
}

__global__ __launch_bounds__(TPB) void graphnorm_kernel(
    const float4* __restrict__ x4,
    const float*  __restrict__ weight,
    const float*  __restrict__ bias,
    float4*       __restrict__ out4)
{
    __shared__ float4 red_s[RG][D4];
    __shared__ float4 red_q[RG][D4];
    __shared__ float4 sc_s[D4];
    __shared__ float4 sh_s[D4];

    const int g   = blockIdx.x;
    const int tid = threadIdx.x;
    const int c4  = tid & (D4 - 1);   // float4 column
    const int rg  = tid >> 5;         // row group 0..15

    const int start = g_seg_off[g];
    const int end   = g_seg_off[g + 1];
    const int cnt   = end - start;

    // ---- Pass 1: per-column sum / sumsq (unroll x2 for MLP) ----
    float4 s = make_float4(0.f, 0.f, 0.f, 0.f);
    float4 q = make_float4(0.f, 0.f, 0.f, 0.f);
    int r = start + rg;
    for (; r + RG < end; r += 2 * RG) {
        float4 v0 = x4[r * D4 + c4];
        float4 v1 = x4[(r + RG) * D4 + c4];
        s.x += v0.x; s.y += v0.y; s.z += v0.z; s.w += v0.w;
        q.x += v0.x * v0.x; q.y += v0.y * v0.y;
        q.z += v0.z * v0.z; q.w += v0.w * v0.w;
        s.x += v1.x; s.y += v1.y; s.z += v1.z; s.w += v1.w;
        q.x += v1.x * v1.x; q.y += v1.y * v1.y;
        q.z += v1.z * v1.z; q.w += v1.w * v1.w;
    }
    if (r < end) {
        float4 v = x4[r * D4 + c4];
        s.x += v.x; s.y += v.y; s.z += v.z; s.w += v.w;
        q.x += v.x * v.x; q.y += v.y * v.y;
        q.z += v.z * v.z; q.w += v.w * v.w;
    }
    red_s[rg][c4] = s;
    red_q[rg][c4] = q;
    __syncthreads();

    #pragma unroll
    for (int h = RG / 2; h >= 1; h >>= 1) {
        if (rg < h) {
            float4 a = red_s[rg][c4], b = red_s[rg + h][c4];
            a.x += b.x; a.y += b.y; a.z += b.z; a.w += b.w;
            red_s[rg][c4] = a;
            float4 c = red_q[rg][c4], d = red_q[rg + h][c4];
            c.x += d.x; c.y += d.y; c.z += d.z; c.w += d.w;
            red_q[rg][c4] = c;
        }
        __syncthreads();
    }

    // ---- Fold into scale/shift (warp 0) ----
    if (rg == 0) {
        float4 w = reinterpret_cast<const float4*>(weight)[c4];
        float4 b = reinterpret_cast<const float4*>(bias)[c4];
        float4 sc, sh;
        if (cnt > 1) {
            float4 S = red_s[0][c4];
            float4 Q = red_q[0][c4];
            float inv_n = 1.0f / (float)cnt;
            float mx = S.x * inv_n, my = S.y * inv_n, mz = S.z * inv_n, mw = S.w * inv_n;
            float vx = Q.x * inv_n - mx * mx;
            float vy = Q.y * inv_n - my * my;
            float vz = Q.z * inv_n - mz * mz;
            float vw = Q.w * inv_n - mw * mw;
            sc.x = w.x * rsqrtf(vx + EPSV);
            sc.y = w.y * rsqrtf(vy + EPSV);
            sc.z = w.z * rsqrtf(vz + EPSV);
            sc.w = w.w * rsqrtf(vw + EPSV);
            sh.x = b.x - mx * sc.x;
            sh.y = b.y - my * sc.y;
            sh.z = b.z - mz * sc.z;
            sh.w = b.w - mw * sc.w;
        } else {
            // cnt <= 1: reference leaves mean=0, var=1
            float rr = rsqrtf(1.0f + EPSV);
            sc.x = w.x * rr; sc.y = w.y * rr; sc.z = w.z * rr; sc.w = w.w * rr;
            sh = b;
        }
        sc_s[c4] = sc;
        sh_s[c4] = sh;
    }
    __syncthreads();

    // ---- Pass 2: normalize. x re-read hits L2; output uses streaming
    //      stores (evict-first) so it doesn't evict x segments from L2. ----
    const int jend = end * D4;
    for (int j = start * D4 + tid; j < jend; j += TPB) {
        int c = j & (D4 - 1);
        float4 v  = x4[j];
        float4 sc = sc_s[c];
        float4 sh = sh_s[c];
        float4 o;
        o.x = v.x * sc.x + sh.x;
        o.y = v.y * sc.y + sh.y;
        o.z = v.z * sc.z + sh.z;
        o.w = v.w * sc.w + sh.w;
        __stcs(&out4[j], o);
    }
}

extern "C" void kernel_launch(void* const* d_in, const int* in_sizes, int n_in,
                              void* d_out, int out_size)
{
    const float* x      = (const float*)d_in[0];
    const int*   batch  = (const int*)d_in[1];   // int32 or int64; detected on device
    const float* weight = (const float*)d_in[2];
    const float* bias   = (const float*)d_in[3];
    float*       out    = (float*)d_out;

    int n = in_sizes[1];  // number of nodes

    offsets_kernel<<<(NUM_G + 1 + 255) / 256, 256>>>(batch, n);
    graphnorm_kernel<<<NUM_G, TPB>>>(
        reinterpret_cast<const float4*>(x), weight, bias,
        reinterpret_cast<float4*>(out));
}